// round 1
// baseline (speedup 1.0000x reference)
#include <cuda_runtime.h>

#define MAXN 50000
#define MAXE 800000
#define MAXB 16

// ---------------- device-global scratch (no allocations allowed) ----------------
__device__ float g_xa[MAXN * 32];
__device__ float g_xb[MAXN * 32];
__device__ float g_s[MAXN * 64];    // x[n] @ W1_edge[0:32,:]   (src block)
__device__ float g_d[MAXN * 64];    // x[n] @ W1_edge[32:64,:]  (dst block)
__device__ float g_agg[MAXN * 32];  // scatter-sum of e -> dst
__device__ float g_u[MAXB * 32];
__device__ float g_bsum[MAXB * 32]; // scatter-sum of x -> batch
__device__ float g_deg[MAXN];
__device__ float g_gcnt[MAXB];
__device__ float g_uWe[MAXB * 64];  // u @ W1_edge[96:128,:] + b1_edge
__device__ float g_uWn[MAXB * 64];  // u @ W1_node[64:96,:]  + b1_node

// ---------------- small utility kernels ----------------
__global__ void zero_k(float* p, int n) {
    int i = blockIdx.x * blockDim.x + threadIdx.x;
    if (i < n) p[i] = 0.f;
}

__global__ void bn_k(const float* __restrict__ x, const float* __restrict__ gamma,
                     const float* __restrict__ beta, float* __restrict__ y, int total) {
    int i = blockIdx.x * blockDim.x + threadIdx.x;
    if (i < total) {
        int c = i & 31;
        y[i] = x[i] * (gamma[c] * rsqrtf(1.f + 1e-5f)) + beta[c];
    }
}

__global__ void deg_k(const int* __restrict__ dst, int E) {
    int e = blockIdx.x * blockDim.x + threadIdx.x;
    if (e < E) atomicAdd(&g_deg[dst[e]], 1.f);
}

__global__ void gcnt_k(const int* __restrict__ batch, int N) {
    __shared__ float sc[MAXB];
    int tid = threadIdx.x;
    if (tid < MAXB) sc[tid] = 0.f;
    __syncthreads();
    int i = blockIdx.x * blockDim.x + tid;
    if (i < N) atomicAdd(&sc[batch[i]], 1.f);
    __syncthreads();
    if (tid < MAXB) atomicAdd(&g_gcnt[tid], sc[tid]);
}

// per-batch u contributions to the edge/node layer-1 activations (+bias)
__global__ void uw_k(const float* __restrict__ eW1u, const float* __restrict__ eb1,
                     const float* __restrict__ nW1u, const float* __restrict__ nb1) {
    int b = blockIdx.x;
    int t = threadIdx.x;
    int j = t & 63;
    const float* uu = g_u + b * 32;
    if (t < 64) {
        float acc = eb1[j];
#pragma unroll
        for (int k = 0; k < 32; k++) acc += uu[k] * eW1u[k * 64 + j];
        g_uWe[b * 64 + j] = acc;
    } else {
        float acc = nb1[j];
#pragma unroll
        for (int k = 0; k < 32; k++) acc += uu[k] * nW1u[k * 64 + j];
        g_uWn[b * 64 + j] = acc;
    }
}

// per-node precompute: s[n] = x[n] @ W1e[0:32,:], d[n] = x[n] @ W1e[32:64,:]
__global__ void __launch_bounds__(256) sd_k(const float* __restrict__ x,
                                            const float* __restrict__ W1sd, int N) {
    __shared__ float sW[64 * 64];
    int tid = threadIdx.x;
    for (int i = tid; i < 4096; i += 256) sW[i] = W1sd[i];
    __syncthreads();
    int n = blockIdx.x * 256 + tid;
    if (n >= N) return;

    float xv[32];
    const float4* xp = (const float4*)(x + (size_t)n * 32);
#pragma unroll
    for (int k = 0; k < 8; k++) {
        float4 v = xp[k];
        xv[4 * k] = v.x; xv[4 * k + 1] = v.y; xv[4 * k + 2] = v.z; xv[4 * k + 3] = v.w;
    }
    float acc[64];
#pragma unroll
    for (int j = 0; j < 64; j++) acc[j] = 0.f;
#pragma unroll 4
    for (int k = 0; k < 32; k++) {
        float xk = xv[k];
#pragma unroll
        for (int j = 0; j < 64; j++) acc[j] += xk * sW[k * 64 + j];
    }
    float4* sp = (float4*)(g_s + (size_t)n * 64);
#pragma unroll
    for (int j = 0; j < 16; j++)
        sp[j] = make_float4(acc[4 * j], acc[4 * j + 1], acc[4 * j + 2], acc[4 * j + 3]);

#pragma unroll
    for (int j = 0; j < 64; j++) acc[j] = 0.f;
#pragma unroll 4
    for (int k = 0; k < 32; k++) {
        float xk = xv[k];
#pragma unroll
        for (int j = 0; j < 64; j++) acc[j] += xk * sW[(32 + k) * 64 + j];
    }
    float4* dp = (float4*)(g_d + (size_t)n * 64);
#pragma unroll
    for (int j = 0; j < 16; j++)
        dp[j] = make_float4(acc[4 * j], acc[4 * j + 1], acc[4 * j + 2], acc[4 * j + 3]);
}

// edge model: e = MLP([x_src, x_dst, e, u[batch_src]]), plus scatter-add to agg[dst]
__global__ void __launch_bounds__(256) edge_k(const int* __restrict__ src,
                                              const int* __restrict__ dstA,
                                              const int* __restrict__ batch,
                                              const float* __restrict__ W1e,  // e-block rows [64:96)
                                              const float* __restrict__ W2,
                                              const float* __restrict__ b2,
                                              float* __restrict__ ebuf, int E) {
    __shared__ float sWe[2048];
    __shared__ float sW2[2048];
    __shared__ float sU[1024];
    __shared__ float sb2[32];
    int tid = threadIdx.x;
    for (int i = tid; i < 2048; i += 256) { sWe[i] = W1e[i]; sW2[i] = W2[i]; }
    for (int i = tid; i < 1024; i += 256) sU[i] = g_uWe[i];
    if (tid < 32) sb2[tid] = b2[tid];
    __syncthreads();

    int e = blockIdx.x * 256 + tid;
    if (e >= E) return;
    int s = src[e], d = dstA[e];
    int bs = batch[s];

    float ev[32];
    {
        const float4* ep = (const float4*)(ebuf + (size_t)e * 32);
#pragma unroll
        for (int k = 0; k < 8; k++) {
            float4 v = ep[k];
            ev[4 * k] = v.x; ev[4 * k + 1] = v.y; ev[4 * k + 2] = v.z; ev[4 * k + 3] = v.w;
        }
    }
    float h[64];
    {
        const float4* spv = (const float4*)(g_s + (size_t)s * 64);
        const float4* dpv = (const float4*)(g_d + (size_t)d * 64);
        const float* up = sU + bs * 64;
#pragma unroll
        for (int j = 0; j < 16; j++) {
            float4 a = spv[j];
            float4 b = dpv[j];
            h[4 * j]     = a.x + b.x + up[4 * j];
            h[4 * j + 1] = a.y + b.y + up[4 * j + 1];
            h[4 * j + 2] = a.z + b.z + up[4 * j + 2];
            h[4 * j + 3] = a.w + b.w + up[4 * j + 3];
        }
    }
#pragma unroll 4
    for (int k = 0; k < 32; k++) {
        float evk = ev[k];
#pragma unroll
        for (int j = 0; j < 64; j++) h[j] += evk * sWe[k * 64 + j];
    }
#pragma unroll
    for (int j = 0; j < 64; j++) h[j] = fmaxf(h[j], 0.f);

    float o[32];
#pragma unroll
    for (int i = 0; i < 32; i++) o[i] = sb2[i];
#pragma unroll 8
    for (int j = 0; j < 64; j++) {
        float hj = h[j];
#pragma unroll
        for (int i = 0; i < 32; i++) o[i] += hj * sW2[j * 32 + i];
    }
    float4* eo = (float4*)(ebuf + (size_t)e * 32);
#pragma unroll
    for (int i = 0; i < 8; i++)
        eo[i] = make_float4(o[4 * i], o[4 * i + 1], o[4 * i + 2], o[4 * i + 3]);
    float* ap = g_agg + (size_t)d * 32;
#pragma unroll
    for (int i = 0; i < 32; i++) atomicAdd(ap + i, o[i]);
}

// node model: x = MLP([x, agg/deg, u[batch]]), plus batch-sum via shared bins
__global__ void __launch_bounds__(256) node_k(const float* __restrict__ x_in,
                                              float* __restrict__ x_out,
                                              const int* __restrict__ batch,
                                              const float* __restrict__ W1n,  // rows [0:64)
                                              const float* __restrict__ W2n,
                                              const float* __restrict__ b2n, int N) {
    __shared__ float sWx[2048];
    __shared__ float sWa[2048];
    __shared__ float sW2[2048];
    __shared__ float sU[1024];
    __shared__ float sb2[32];
    __shared__ float sB[MAXB * 32];
    int tid = threadIdx.x;
    for (int i = tid; i < 2048; i += 256) {
        sWx[i] = W1n[i];
        sWa[i] = W1n[2048 + i];
        sW2[i] = W2n[i];
    }
    for (int i = tid; i < 1024; i += 256) sU[i] = g_uWn[i];
    if (tid < 32) sb2[tid] = b2n[tid];
    for (int i = tid; i < MAXB * 32; i += 256) sB[i] = 0.f;
    __syncthreads();

    int n = blockIdx.x * 256 + tid;
    if (n < N) {
        int b = batch[n];
        float xv[32], av[32];
        float inv = 1.f / fmaxf(g_deg[n], 1.f);
        const float4* xp = (const float4*)(x_in + (size_t)n * 32);
        const float4* ap = (const float4*)(g_agg + (size_t)n * 32);
#pragma unroll
        for (int k = 0; k < 8; k++) {
            float4 v = xp[k];
            xv[4 * k] = v.x; xv[4 * k + 1] = v.y; xv[4 * k + 2] = v.z; xv[4 * k + 3] = v.w;
            float4 a = ap[k];
            av[4 * k] = a.x * inv; av[4 * k + 1] = a.y * inv;
            av[4 * k + 2] = a.z * inv; av[4 * k + 3] = a.w * inv;
        }
        float h[64];
        const float* up = sU + b * 64;
#pragma unroll
        for (int j = 0; j < 64; j++) h[j] = up[j];
#pragma unroll 4
        for (int k = 0; k < 32; k++) {
            float xk = xv[k], ak = av[k];
#pragma unroll
            for (int j = 0; j < 64; j++) h[j] += xk * sWx[k * 64 + j] + ak * sWa[k * 64 + j];
        }
#pragma unroll
        for (int j = 0; j < 64; j++) h[j] = fmaxf(h[j], 0.f);

        float o[32];
#pragma unroll
        for (int i = 0; i < 32; i++) o[i] = sb2[i];
#pragma unroll 8
        for (int j = 0; j < 64; j++) {
            float hj = h[j];
#pragma unroll
            for (int i = 0; i < 32; i++) o[i] += hj * sW2[j * 32 + i];
        }
        float4* xo = (float4*)(x_out + (size_t)n * 32);
#pragma unroll
        for (int i = 0; i < 8; i++)
            xo[i] = make_float4(o[4 * i], o[4 * i + 1], o[4 * i + 2], o[4 * i + 3]);
        float* bp = sB + b * 32;
#pragma unroll
        for (int i = 0; i < 32; i++) atomicAdd(bp + i, o[i]);
    }
    __syncthreads();
    for (int i = tid; i < MAXB * 32; i += 256) atomicAdd(&g_bsum[i], sB[i]);
}

// global model: u = MLP([u, bsum/gcnt])
__global__ void glob_k(const float* __restrict__ W1g, const float* __restrict__ b1g,
                       const float* __restrict__ W2g, const float* __restrict__ b2g,
                       float* __restrict__ out_u, int writeOut) {
    int b = blockIdx.x;
    int j = threadIdx.x;  // 64 threads
    __shared__ float gi[64];
    __shared__ float h[64];
    if (j < 32) gi[j] = g_u[b * 32 + j];
    else        gi[j] = g_bsum[b * 32 + (j - 32)] / fmaxf(g_gcnt[b], 1.f);
    __syncthreads();
    float acc = b1g[j];
#pragma unroll
    for (int k = 0; k < 64; k++) acc += gi[k] * W1g[k * 64 + j];
    h[j] = fmaxf(acc, 0.f);
    __syncthreads();
    if (j < 32) {
        float a2 = b2g[j];
#pragma unroll
        for (int k = 0; k < 64; k++) a2 += h[k] * W2g[k * 32 + j];
        g_u[b * 32 + j] = a2;
        if (writeOut) out_u[b * 32 + j] = a2;
    }
}

// ---------------- host launcher ----------------
extern "C" void kernel_launch(void* const* d_in, const int* in_sizes, int n_in,
                              void* d_out, int out_size) {
    const float* node_feats = (const float*)d_in[0];
    const int*   edge_index = (const int*)d_in[1];
    const float* edge_feats = (const float*)d_in[2];
    const float* glob_feats = (const float*)d_in[3];
    const int*   batch      = (const int*)d_in[4];
    const float* node_gamma = (const float*)d_in[5];
    const float* node_beta  = (const float*)d_in[6];
    const float* edge_gamma = (const float*)d_in[7];
    const float* edge_beta  = (const float*)d_in[8];
    const float* glob_gamma = (const float*)d_in[9];
    const float* glob_beta  = (const float*)d_in[10];
    const float* edge_W1 = (const float*)d_in[11];
    const float* edge_b1 = (const float*)d_in[12];
    const float* edge_W2 = (const float*)d_in[13];
    const float* edge_b2 = (const float*)d_in[14];
    const float* node_W1 = (const float*)d_in[15];
    const float* node_b1 = (const float*)d_in[16];
    const float* node_W2 = (const float*)d_in[17];
    const float* node_b2 = (const float*)d_in[18];
    const float* glob_W1 = (const float*)d_in[19];
    const float* glob_b1 = (const float*)d_in[20];
    const float* glob_W2 = (const float*)d_in[21];
    const float* glob_b2 = (const float*)d_in[22];

    const int N = in_sizes[0] / 32;
    const int E = in_sizes[1] / 2;
    const int B = in_sizes[3] / 32;
    const int* srcA = edge_index;
    const int* dstA = edge_index + E;

    float* out   = (float*)d_out;
    float* out_x = out;
    float* out_e = out + (size_t)N * 32;
    float* out_u = out_e + (size_t)E * 32;

    float *xa, *xb, *up, *degp, *gcntp, *aggp, *bsump;
    cudaGetSymbolAddress((void**)&xa, g_xa);
    cudaGetSymbolAddress((void**)&xb, g_xb);
    cudaGetSymbolAddress((void**)&up, g_u);
    cudaGetSymbolAddress((void**)&degp, g_deg);
    cudaGetSymbolAddress((void**)&gcntp, g_gcnt);
    cudaGetSymbolAddress((void**)&aggp, g_agg);
    cudaGetSymbolAddress((void**)&bsump, g_bsum);

    // input BN
    bn_k<<<(N * 32 + 255) / 256, 256>>>(node_feats, node_gamma, node_beta, xa, N * 32);
    bn_k<<<(E * 32 + 255) / 256, 256>>>(edge_feats, edge_gamma, edge_beta, out_e, E * 32);
    bn_k<<<(B * 32 + 255) / 256, 256>>>(glob_feats, glob_gamma, glob_beta, up, B * 32);

    // fixed index-structure denominators
    zero_k<<<(N + 255) / 256, 256>>>(degp, N);
    zero_k<<<1, 256>>>(gcntp, B);
    deg_k<<<(E + 255) / 256, 256>>>(dstA, E);
    gcnt_k<<<(N + 255) / 256, 256>>>(batch, N);

    float* xcur = xa;
    for (int l = 0; l < 3; l++) {
        float* xnext = (l == 2) ? out_x : ((xcur == xa) ? xb : xa);

        zero_k<<<(N * 32 + 255) / 256, 256>>>(aggp, N * 32);
        zero_k<<<1, 512>>>(bsump, B * 32);

        uw_k<<<B, 128>>>(edge_W1 + l * 8192 + 96 * 64, edge_b1 + l * 64,
                         node_W1 + l * 6144 + 64 * 64, node_b1 + l * 64);
        sd_k<<<(N + 255) / 256, 256>>>(xcur, edge_W1 + l * 8192, N);
        edge_k<<<(E + 255) / 256, 256>>>(srcA, dstA, batch,
                                         edge_W1 + l * 8192 + 64 * 64,
                                         edge_W2 + l * 2048, edge_b2 + l * 32, out_e, E);
        node_k<<<(N + 255) / 256, 256>>>(xcur, xnext, batch,
                                         node_W1 + l * 6144,
                                         node_W2 + l * 2048, node_b2 + l * 32, N);
        glob_k<<<B, 64>>>(glob_W1 + l * 4096, glob_b1 + l * 64,
                          glob_W2 + l * 2048, glob_b2 + l * 32, out_u, (l == 2) ? 1 : 0);
        xcur = xnext;
    }
}

// round 4
// speedup vs baseline: 1.8236x; 1.8236x over previous
#include <cuda_runtime.h>

#define MAXN 50000
#define MAXB 16

// ---------------- device-global scratch (no allocations allowed) ----------------
__device__ float g_xa[MAXN * 32];
__device__ float g_xb[MAXN * 32];
__device__ float g_s[MAXN * 64];    // x[n] @ W1_edge[0:32,:]   (src block)
__device__ float g_d[MAXN * 64];    // x[n] @ W1_edge[32:64,:]  (dst block)
__device__ float g_agg[MAXN * 32];  // scatter-sum of e -> dst
__device__ float g_u[MAXB * 32];
__device__ float g_bsum[MAXB * 32]; // scatter-sum of x -> batch
__device__ float g_deg[MAXN];
__device__ float g_gcnt[MAXB];
__device__ float g_uWe[MAXB * 64];  // u @ W1_edge[96:128,:] + b1_edge
__device__ float g_uWn[MAXB * 64];  // u @ W1_node[64:96,:]  + b1_node

// ---------------- small utility kernels ----------------
__global__ void zero_k(float* p, int n) {
    int i = blockIdx.x * blockDim.x + threadIdx.x;
    if (i < n) p[i] = 0.f;
}

__global__ void bn_k(const float* __restrict__ x, const float* __restrict__ gamma,
                     const float* __restrict__ beta, float* __restrict__ y, int total) {
    int i = blockIdx.x * blockDim.x + threadIdx.x;
    if (i < total) {
        int c = i & 31;
        y[i] = x[i] * (gamma[c] * rsqrtf(1.f + 1e-5f)) + beta[c];
    }
}

__global__ void deg_k(const int* __restrict__ dst, int E) {
    int e = blockIdx.x * blockDim.x + threadIdx.x;
    if (e < E) atomicAdd(&g_deg[dst[e]], 1.f);
}

__global__ void gcnt_k(const int* __restrict__ batch, int N) {
    __shared__ float sc[MAXB];
    int tid = threadIdx.x;
    if (tid < MAXB) sc[tid] = 0.f;
    __syncthreads();
    int i = blockIdx.x * blockDim.x + tid;
    if (i < N) atomicAdd(&sc[batch[i]], 1.f);
    __syncthreads();
    if (tid < MAXB) atomicAdd(&g_gcnt[tid], sc[tid]);
}

// per-batch u contributions to the edge/node layer-1 activations (+bias)
__global__ void uw_k(const float* __restrict__ eW1u, const float* __restrict__ eb1,
                     const float* __restrict__ nW1u, const float* __restrict__ nb1) {
    int b = blockIdx.x;
    int t = threadIdx.x;
    int j = t & 63;
    const float* uu = g_u + b * 32;
    if (t < 64) {
        float acc = eb1[j];
#pragma unroll
        for (int k = 0; k < 32; k++) acc += uu[k] * eW1u[k * 64 + j];
        g_uWe[b * 64 + j] = acc;
    } else {
        float acc = nb1[j];
#pragma unroll
        for (int k = 0; k < 32; k++) acc += uu[k] * nW1u[k * 64 + j];
        g_uWn[b * 64 + j] = acc;
    }
}

// per-node precompute: s[n] = x[n] @ W1e[0:32,:], d[n] = x[n] @ W1e[32:64,:]
__global__ void __launch_bounds__(256) sd_k(const float* __restrict__ x,
                                            const float* __restrict__ W1sd, int N) {
    __shared__ float sW[64 * 64];
    int tid = threadIdx.x;
    for (int i = tid; i < 4096; i += 256) sW[i] = W1sd[i];
    __syncthreads();
    int n = blockIdx.x * 256 + tid;
    if (n >= N) return;

    float xv[32];
    const float4* xp = (const float4*)(x + (size_t)n * 32);
#pragma unroll
    for (int k = 0; k < 8; k++) {
        float4 v = xp[k];
        xv[4 * k] = v.x; xv[4 * k + 1] = v.y; xv[4 * k + 2] = v.z; xv[4 * k + 3] = v.w;
    }
    float acc[64];
#pragma unroll
    for (int j = 0; j < 64; j++) acc[j] = 0.f;
#pragma unroll 4
    for (int k = 0; k < 32; k++) {
        float xk = xv[k];
#pragma unroll
        for (int j = 0; j < 64; j++) acc[j] += xk * sW[k * 64 + j];
    }
    float4* sp = (float4*)(g_s + (size_t)n * 64);
#pragma unroll
    for (int j = 0; j < 16; j++)
        sp[j] = make_float4(acc[4 * j], acc[4 * j + 1], acc[4 * j + 2], acc[4 * j + 3]);

#pragma unroll
    for (int j = 0; j < 64; j++) acc[j] = 0.f;
#pragma unroll 4
    for (int k = 0; k < 32; k++) {
        float xk = xv[k];
#pragma unroll
        for (int j = 0; j < 64; j++) acc[j] += xk * sW[(32 + k) * 64 + j];
    }
    float4* dp = (float4*)(g_d + (size_t)n * 64);
#pragma unroll
    for (int j = 0; j < 16; j++)
        dp[j] = make_float4(acc[4 * j], acc[4 * j + 1], acc[4 * j + 2], acc[4 * j + 3]);
}

// ---------------- tiled edge kernel: 128 edges per 256-thread block ----------------
#define TE 128

struct ESm {
    float sWe[32 * 64];    // W1 e-block (rows 64..96)
    float sW2[64 * 32];
    float sU[MAXB * 64];
    float sb2[32];
    float sEin[TE * 36];   // edge feats, row stride 36
    float sH[TE * 68];     // hidden, row stride 68
    int sSrc[TE];
    int sDst[TE];
    int sBs[TE];
};

__global__ void __launch_bounds__(256, 2) edge2_k(
    const int* __restrict__ src, const int* __restrict__ dstA,
    const int* __restrict__ batch,
    const float* __restrict__ W1e, const float* __restrict__ W2,
    const float* __restrict__ b2,
    const float* __restrict__ ein,          // raw edge feats (l0) or current e
    const float* __restrict__ bn_gamma,     // non-null => apply BN to ein
    const float* __restrict__ bn_beta,
    float* __restrict__ eout, int E) {
    extern __shared__ char smem_raw[];
    ESm& sm = *(ESm*)smem_raw;

    int tid = threadIdx.x;
    int eBase = blockIdx.x * TE;

    // ---- stage weights / tables ----
    for (int i = tid; i < 2048; i += 256) { sm.sWe[i] = W1e[i]; sm.sW2[i] = W2[i]; }
    for (int i = tid; i < MAXB * 64; i += 256) sm.sU[i] = g_uWe[i];
    if (tid < 32) sm.sb2[tid] = b2[tid];

    // ---- stage indices ----
    if (tid < TE) {
        int e = eBase + tid;
        int s = 0, d = 0, bs = 0;
        if (e < E) { s = src[e]; d = dstA[e]; bs = batch[s]; }
        sm.sSrc[tid] = s; sm.sDst[tid] = d; sm.sBs[tid] = bs;
    }

    // ---- stage edge features (optionally with BN), 2 threads per edge ----
    {
        int el = tid >> 1;
        int e = eBase + el;
        int off = (tid & 1) * 16;
        if (e < E) {
            const float4* p = (const float4*)(ein + (size_t)e * 32 + off);
#pragma unroll
            for (int q = 0; q < 4; q++) {
                float4 v = p[q];
                if (bn_gamma) {
                    int c = off + 4 * q;
                    float r = rsqrtf(1.f + 1e-5f);
                    v.x = v.x * (__ldg(bn_gamma + c)     * r) + __ldg(bn_beta + c);
                    v.y = v.y * (__ldg(bn_gamma + c + 1) * r) + __ldg(bn_beta + c + 1);
                    v.z = v.z * (__ldg(bn_gamma + c + 2) * r) + __ldg(bn_beta + c + 2);
                    v.w = v.w * (__ldg(bn_gamma + c + 3) * r) + __ldg(bn_beta + c + 3);
                }
                *(float4*)&sm.sEin[el * 36 + off + 4 * q] = v;
            }
        }
    }
    __syncthreads();

    // ---- GEMM1: H[128x64] = relu(s[src]+d[dst]+uWe[bs] + Ein[128x32] @ We[32x64]) ----
    {
        int tx = tid & 15, ty = tid >> 4;
        int r0 = ty * 8, c0 = tx * 4;
        float4 acc[8];
#pragma unroll
        for (int i = 0; i < 8; i++) {
            int s = sm.sSrc[r0 + i], d = sm.sDst[r0 + i], bs = sm.sBs[r0 + i];
            float4 a = *(const float4*)(g_s + (size_t)s * 64 + c0);
            float4 b = *(const float4*)(g_d + (size_t)d * 64 + c0);
            const float* up = sm.sU + bs * 64 + c0;
            acc[i].x = a.x + b.x + up[0];
            acc[i].y = a.y + b.y + up[1];
            acc[i].z = a.z + b.z + up[2];
            acc[i].w = a.w + b.w + up[3];
        }
#pragma unroll
        for (int k = 0; k < 32; k++) {
            float4 w = *(float4*)&sm.sWe[k * 64 + c0];
#pragma unroll
            for (int i = 0; i < 8; i++) {
                float ev = sm.sEin[(r0 + i) * 36 + k];
                acc[i].x += ev * w.x;
                acc[i].y += ev * w.y;
                acc[i].z += ev * w.z;
                acc[i].w += ev * w.w;
            }
        }
#pragma unroll
        for (int i = 0; i < 8; i++) {
            acc[i].x = fmaxf(acc[i].x, 0.f);
            acc[i].y = fmaxf(acc[i].y, 0.f);
            acc[i].z = fmaxf(acc[i].z, 0.f);
            acc[i].w = fmaxf(acc[i].w, 0.f);
            *(float4*)&sm.sH[(r0 + i) * 68 + c0] = acc[i];
        }
    }
    __syncthreads();

    // ---- GEMM2: O[128x32] = H @ W2[64x32] + b2; write e; scatter-add to agg ----
    {
        int tx2 = tid & 7, ty2 = tid >> 3;
        int r0 = ty2 * 4, c0 = tx2 * 4;
        float4 o[4];
        float4 bb = *(float4*)&sm.sb2[c0];
#pragma unroll
        for (int i = 0; i < 4; i++) o[i] = bb;
#pragma unroll
        for (int k = 0; k < 64; k++) {
            float4 w = *(float4*)&sm.sW2[k * 32 + c0];
#pragma unroll
            for (int i = 0; i < 4; i++) {
                float hv = sm.sH[(r0 + i) * 68 + k];
                o[i].x += hv * w.x;
                o[i].y += hv * w.y;
                o[i].z += hv * w.z;
                o[i].w += hv * w.w;
            }
        }
#pragma unroll
        for (int i = 0; i < 4; i++) {
            int e = eBase + r0 + i;
            if (e < E) {
                *(float4*)(eout + (size_t)e * 32 + c0) = o[i];
                float* ap = g_agg + (size_t)sm.sDst[r0 + i] * 32 + c0;
                asm volatile("red.global.add.v4.f32 [%0], {%1,%2,%3,%4};"
                             :: "l"(ap), "f"(o[i].x), "f"(o[i].y), "f"(o[i].z), "f"(o[i].w)
                             : "memory");
            }
        }
    }
}

// node model: x = MLP([x, agg/deg, u[batch]]), plus batch-sum via shared bins
__global__ void __launch_bounds__(256) node_k(const float* __restrict__ x_in,
                                              float* __restrict__ x_out,
                                              const int* __restrict__ batch,
                                              const float* __restrict__ W1n,  // rows [0:64)
                                              const float* __restrict__ W2n,
                                              const float* __restrict__ b2n, int N) {
    __shared__ float sWx[2048];
    __shared__ float sWa[2048];
    __shared__ float sW2[2048];
    __shared__ float sU[1024];
    __shared__ float sb2[32];
    __shared__ float sB[MAXB * 32];
    int tid = threadIdx.x;
    for (int i = tid; i < 2048; i += 256) {
        sWx[i] = W1n[i];
        sWa[i] = W1n[2048 + i];
        sW2[i] = W2n[i];
    }
    for (int i = tid; i < 1024; i += 256) sU[i] = g_uWn[i];
    if (tid < 32) sb2[tid] = b2n[tid];
    for (int i = tid; i < MAXB * 32; i += 256) sB[i] = 0.f;
    __syncthreads();

    int n = blockIdx.x * 256 + tid;
    if (n < N) {
        int b = batch[n];
        float xv[32], av[32];
        float inv = 1.f / fmaxf(g_deg[n], 1.f);
        const float4* xp = (const float4*)(x_in + (size_t)n * 32);
        const float4* ap = (const float4*)(g_agg + (size_t)n * 32);
#pragma unroll
        for (int k = 0; k < 8; k++) {
            float4 v = xp[k];
            xv[4 * k] = v.x; xv[4 * k + 1] = v.y; xv[4 * k + 2] = v.z; xv[4 * k + 3] = v.w;
            float4 a = ap[k];
            av[4 * k] = a.x * inv; av[4 * k + 1] = a.y * inv;
            av[4 * k + 2] = a.z * inv; av[4 * k + 3] = a.w * inv;
        }
        float h[64];
        const float* up = sU + b * 64;
#pragma unroll
        for (int j = 0; j < 64; j++) h[j] = up[j];
#pragma unroll 4
        for (int k = 0; k < 32; k++) {
            float xk = xv[k], ak = av[k];
#pragma unroll
            for (int j = 0; j < 64; j++) h[j] += xk * sWx[k * 64 + j] + ak * sWa[k * 64 + j];
        }
#pragma unroll
        for (int j = 0; j < 64; j++) h[j] = fmaxf(h[j], 0.f);

        float o[32];
#pragma unroll
        for (int i = 0; i < 32; i++) o[i] = sb2[i];
#pragma unroll 8
        for (int j = 0; j < 64; j++) {
            float hj = h[j];
#pragma unroll
            for (int i = 0; i < 32; i++) o[i] += hj * sW2[j * 32 + i];
        }
        float4* xo = (float4*)(x_out + (size_t)n * 32);
#pragma unroll
        for (int i = 0; i < 8; i++)
            xo[i] = make_float4(o[4 * i], o[4 * i + 1], o[4 * i + 2], o[4 * i + 3]);
        float* bp = sB + b * 32;
#pragma unroll
        for (int i = 0; i < 32; i++) atomicAdd(bp + i, o[i]);
    }
    __syncthreads();
    for (int i = tid; i < MAXB * 32; i += 256) atomicAdd(&g_bsum[i], sB[i]);
}

// global model: u = MLP([u, bsum/gcnt])
__global__ void glob_k(const float* __restrict__ W1g, const float* __restrict__ b1g,
                       const float* __restrict__ W2g, const float* __restrict__ b2g,
                       float* __restrict__ out_u, int writeOut) {
    int b = blockIdx.x;
    int j = threadIdx.x;  // 64 threads
    __shared__ float gi[64];
    __shared__ float h[64];
    if (j < 32) gi[j] = g_u[b * 32 + j];
    else        gi[j] = g_bsum[b * 32 + (j - 32)] / fmaxf(g_gcnt[b], 1.f);
    __syncthreads();
    float acc = b1g[j];
#pragma unroll
    for (int k = 0; k < 64; k++) acc += gi[k] * W1g[k * 64 + j];
    h[j] = fmaxf(acc, 0.f);
    __syncthreads();
    if (j < 32) {
        float a2 = b2g[j];
#pragma unroll
        for (int k = 0; k < 64; k++) a2 += h[k] * W2g[k * 32 + j];
        g_u[b * 32 + j] = a2;
        if (writeOut) out_u[b * 32 + j] = a2;
    }
}

// ---------------- host launcher ----------------
extern "C" void kernel_launch(void* const* d_in, const int* in_sizes, int n_in,
                              void* d_out, int out_size) {
    const float* node_feats = (const float*)d_in[0];
    const int*   edge_index = (const int*)d_in[1];
    const float* edge_feats = (const float*)d_in[2];
    const float* glob_feats = (const float*)d_in[3];
    const int*   batch      = (const int*)d_in[4];
    const float* node_gamma = (const float*)d_in[5];
    const float* node_beta  = (const float*)d_in[6];
    const float* edge_gamma = (const float*)d_in[7];
    const float* edge_beta  = (const float*)d_in[8];
    const float* glob_gamma = (const float*)d_in[9];
    const float* glob_beta  = (const float*)d_in[10];
    const float* edge_W1 = (const float*)d_in[11];
    const float* edge_b1 = (const float*)d_in[12];
    const float* edge_W2 = (const float*)d_in[13];
    const float* edge_b2 = (const float*)d_in[14];
    const float* node_W1 = (const float*)d_in[15];
    const float* node_b1 = (const float*)d_in[16];
    const float* node_W2 = (const float*)d_in[17];
    const float* node_b2 = (const float*)d_in[18];
    const float* glob_W1 = (const float*)d_in[19];
    const float* glob_b1 = (const float*)d_in[20];
    const float* glob_W2 = (const float*)d_in[21];
    const float* glob_b2 = (const float*)d_in[22];

    const int N = in_sizes[0] / 32;
    const int E = in_sizes[1] / 2;
    const int B = in_sizes[3] / 32;
    const int* srcA = edge_index;
    const int* dstA = edge_index + E;

    float* out   = (float*)d_out;
    float* out_x = out;
    float* out_e = out + (size_t)N * 32;
    float* out_u = out_e + (size_t)E * 32;

    float *xa, *xb, *up, *degp, *gcntp, *aggp, *bsump;
    cudaGetSymbolAddress((void**)&xa, g_xa);
    cudaGetSymbolAddress((void**)&xb, g_xb);
    cudaGetSymbolAddress((void**)&up, g_u);
    cudaGetSymbolAddress((void**)&degp, g_deg);
    cudaGetSymbolAddress((void**)&gcntp, g_gcnt);
    cudaGetSymbolAddress((void**)&aggp, g_agg);
    cudaGetSymbolAddress((void**)&bsump, g_bsum);

    static bool attr_set = false;
    if (!attr_set) {
        cudaFuncSetAttribute(edge2_k, cudaFuncAttributeMaxDynamicSharedMemorySize,
                             (int)sizeof(ESm));
        attr_set = true;
    }

    // input BN (node, global; edge BN fused into layer-0 edge kernel)
    bn_k<<<(N * 32 + 255) / 256, 256>>>(node_feats, node_gamma, node_beta, xa, N * 32);
    bn_k<<<(B * 32 + 255) / 256, 256>>>(glob_feats, glob_gamma, glob_beta, up, B * 32);

    // fixed index-structure denominators
    zero_k<<<(N + 255) / 256, 256>>>(degp, N);
    zero_k<<<1, 256>>>(gcntp, B);
    deg_k<<<(E + 255) / 256, 256>>>(dstA, E);
    gcnt_k<<<(N + 255) / 256, 256>>>(batch, N);

    float* xcur = xa;
    int eblocks = (E + TE - 1) / TE;
    for (int l = 0; l < 3; l++) {
        float* xnext = (l == 2) ? out_x : ((xcur == xa) ? xb : xa);

        zero_k<<<(N * 32 + 255) / 256, 256>>>(aggp, N * 32);
        zero_k<<<1, 512>>>(bsump, B * 32);

        uw_k<<<B, 128>>>(edge_W1 + l * 8192 + 96 * 64, edge_b1 + l * 64,
                         node_W1 + l * 6144 + 64 * 64, node_b1 + l * 64);
        sd_k<<<(N + 255) / 256, 256>>>(xcur, edge_W1 + l * 8192, N);
        edge2_k<<<eblocks, 256, sizeof(ESm)>>>(
            srcA, dstA, batch,
            edge_W1 + l * 8192 + 64 * 64,
            edge_W2 + l * 2048, edge_b2 + l * 32,
            (l == 0) ? edge_feats : out_e,
            (l == 0) ? edge_gamma : nullptr,
            (l == 0) ? edge_beta : nullptr,
            out_e, E);
        node_k<<<(N + 255) / 256, 256>>>(xcur, xnext, batch,
                                         node_W1 + l * 6144,
                                         node_W2 + l * 2048, node_b2 + l * 32, N);
        glob_k<<<B, 64>>>(glob_W1 + l * 4096, glob_b1 + l * 64,
                          glob_W2 + l * 2048, glob_b2 + l * 32, out_u, (l == 2) ? 1 : 0);
        xcur = xnext;
    }
}

// round 5
// speedup vs baseline: 1.8524x; 1.0158x over previous
#include <cuda_runtime.h>

#define MAXN 50000
#define MAXB 16

typedef unsigned long long ull;

// packed f32x2 helpers (Blackwell double-rate fp32 path — ptxas never auto-emits)
#define PK2(out, lo, hi) asm("mov.b64 %0, {%1, %2};" : "=l"(out) : "f"(lo), "f"(hi))
#define UPK2(lo, hi, in) asm("mov.b64 {%0, %1}, %2;" : "=f"(lo), "=f"(hi) : "l"(in))
#define FMA2(d, a, b, c) asm("fma.rn.f32x2 %0, %1, %2, %3;" : "=l"(d) : "l"(a), "l"(b), "l"(c))

union F4U { float4 f; ull u[2]; };

// ---------------- device-global scratch (no allocations allowed) ----------------
__device__ float g_xa[MAXN * 32];
__device__ float g_xb[MAXN * 32];
__device__ float g_s[MAXN * 64];    // x[n] @ W1_edge[0:32,:]   (src block)
__device__ float g_d[MAXN * 64];    // x[n] @ W1_edge[32:64,:]  (dst block)
__device__ float g_agg[MAXN * 32];  // scatter-sum of e -> dst
__device__ float g_u[MAXB * 32];
__device__ float g_bsum[MAXB * 32]; // scatter-sum of x -> batch
__device__ float g_deg[MAXN];
__device__ float g_gcnt[MAXB];
__device__ float g_uWe[MAXB * 64];  // u @ W1_edge[96:128,:] + b1_edge
__device__ float g_uWn[MAXB * 64];  // u @ W1_node[64:96,:]  + b1_node

// ---------------- small utility kernels ----------------
__global__ void zero_k(float* p, int n) {
    int i = blockIdx.x * blockDim.x + threadIdx.x;
    if (i < n) p[i] = 0.f;
}

__global__ void bn_k(const float* __restrict__ x, const float* __restrict__ gamma,
                     const float* __restrict__ beta, float* __restrict__ y, int total) {
    int i = blockIdx.x * blockDim.x + threadIdx.x;
    if (i < total) {
        int c = i & 31;
        y[i] = x[i] * (gamma[c] * rsqrtf(1.f + 1e-5f)) + beta[c];
    }
}

__global__ void deg_k(const int* __restrict__ dst, int E) {
    int e = blockIdx.x * blockDim.x + threadIdx.x;
    if (e < E) atomicAdd(&g_deg[dst[e]], 1.f);
}

__global__ void gcnt_k(const int* __restrict__ batch, int N) {
    __shared__ float sc[MAXB];
    int tid = threadIdx.x;
    if (tid < MAXB) sc[tid] = 0.f;
    __syncthreads();
    int i = blockIdx.x * blockDim.x + tid;
    if (i < N) atomicAdd(&sc[batch[i]], 1.f);
    __syncthreads();
    if (tid < MAXB) atomicAdd(&g_gcnt[tid], sc[tid]);
}

// per-batch u contributions to the edge/node layer-1 activations (+bias)
__global__ void uw_k(const float* __restrict__ eW1u, const float* __restrict__ eb1,
                     const float* __restrict__ nW1u, const float* __restrict__ nb1) {
    int b = blockIdx.x;
    int t = threadIdx.x;
    int j = t & 63;
    const float* uu = g_u + b * 32;
    if (t < 64) {
        float acc = eb1[j];
#pragma unroll
        for (int k = 0; k < 32; k++) acc += uu[k] * eW1u[k * 64 + j];
        g_uWe[b * 64 + j] = acc;
    } else {
        float acc = nb1[j];
#pragma unroll
        for (int k = 0; k < 32; k++) acc += uu[k] * nW1u[k * 64 + j];
        g_uWn[b * 64 + j] = acc;
    }
}

// per-node precompute: s[n] = x[n] @ W1e[0:32,:], d[n] = x[n] @ W1e[32:64,:]
__global__ void __launch_bounds__(256) sd_k(const float* __restrict__ x,
                                            const float* __restrict__ W1sd, int N) {
    __shared__ float sW[64 * 64];
    int tid = threadIdx.x;
    for (int i = tid; i < 4096; i += 256) sW[i] = W1sd[i];
    __syncthreads();
    int n = blockIdx.x * 256 + tid;
    if (n >= N) return;

    float xv[32];
    const float4* xp = (const float4*)(x + (size_t)n * 32);
#pragma unroll
    for (int k = 0; k < 8; k++) {
        float4 v = xp[k];
        xv[4 * k] = v.x; xv[4 * k + 1] = v.y; xv[4 * k + 2] = v.z; xv[4 * k + 3] = v.w;
    }

    ull acc[32];
#pragma unroll
    for (int j = 0; j < 32; j++) acc[j] = 0ull;
#pragma unroll 4
    for (int k = 0; k < 32; k++) {
        ull xkp; PK2(xkp, xv[k], xv[k]);
#pragma unroll
        for (int j4 = 0; j4 < 16; j4++) {
            F4U w; w.f = *(const float4*)&sW[k * 64 + j4 * 4];
            FMA2(acc[2 * j4], xkp, w.u[0], acc[2 * j4]);
            FMA2(acc[2 * j4 + 1], xkp, w.u[1], acc[2 * j4 + 1]);
        }
    }
    float4* sp = (float4*)(g_s + (size_t)n * 64);
#pragma unroll
    for (int j4 = 0; j4 < 16; j4++) {
        F4U o; o.u[0] = acc[2 * j4]; o.u[1] = acc[2 * j4 + 1];
        sp[j4] = o.f;
    }

#pragma unroll
    for (int j = 0; j < 32; j++) acc[j] = 0ull;
#pragma unroll 4
    for (int k = 0; k < 32; k++) {
        ull xkp; PK2(xkp, xv[k], xv[k]);
#pragma unroll
        for (int j4 = 0; j4 < 16; j4++) {
            F4U w; w.f = *(const float4*)&sW[(32 + k) * 64 + j4 * 4];
            FMA2(acc[2 * j4], xkp, w.u[0], acc[2 * j4]);
            FMA2(acc[2 * j4 + 1], xkp, w.u[1], acc[2 * j4 + 1]);
        }
    }
    float4* dp = (float4*)(g_d + (size_t)n * 64);
#pragma unroll
    for (int j4 = 0; j4 < 16; j4++) {
        F4U o; o.u[0] = acc[2 * j4]; o.u[1] = acc[2 * j4 + 1];
        dp[j4] = o.f;
    }
}

// ---------------- tiled edge kernel: 128 edges per 256-thread block ----------------
#define TE 128

struct ESm {
    float sWe[32 * 64];    // W1 e-block (rows 64..96)
    float sW2[64 * 32];
    float sU[MAXB * 64];
    float sb2[32];
    float sEin[TE * 36];   // edge feats, row stride 36
    float sH[TE * 68];     // hidden, row stride 68
    int sSrc[TE];
    int sDst[TE];
    int sBs[TE];
};

__global__ void __launch_bounds__(256, 2) edge2_k(
    const int* __restrict__ src, const int* __restrict__ dstA,
    const int* __restrict__ batch,
    const float* __restrict__ W1e, const float* __restrict__ W2,
    const float* __restrict__ b2,
    const float* __restrict__ ein,          // raw edge feats (l0) or current e
    const float* __restrict__ bn_gamma,     // non-null => apply BN to ein
    const float* __restrict__ bn_beta,
    float* __restrict__ eout, int E) {
    extern __shared__ char smem_raw[];
    ESm& sm = *(ESm*)smem_raw;

    int tid = threadIdx.x;
    int eBase = blockIdx.x * TE;

    // ---- stage weights / tables ----
    for (int i = tid; i < 2048; i += 256) { sm.sWe[i] = W1e[i]; sm.sW2[i] = W2[i]; }
    for (int i = tid; i < MAXB * 64; i += 256) sm.sU[i] = g_uWe[i];
    if (tid < 32) sm.sb2[tid] = b2[tid];

    // ---- stage indices ----
    if (tid < TE) {
        int e = eBase + tid;
        int s = 0, d = 0, bs = 0;
        if (e < E) { s = src[e]; d = dstA[e]; bs = batch[s]; }
        sm.sSrc[tid] = s; sm.sDst[tid] = d; sm.sBs[tid] = bs;
    }

    // ---- stage edge features (optionally with BN), 2 threads per edge ----
    {
        int el = tid >> 1;
        int e = eBase + el;
        int off = (tid & 1) * 16;
        if (e < E) {
            const float4* p = (const float4*)(ein + (size_t)e * 32 + off);
#pragma unroll
            for (int q = 0; q < 4; q++) {
                float4 v = p[q];
                if (bn_gamma) {
                    int c = off + 4 * q;
                    float r = rsqrtf(1.f + 1e-5f);
                    v.x = v.x * (__ldg(bn_gamma + c)     * r) + __ldg(bn_beta + c);
                    v.y = v.y * (__ldg(bn_gamma + c + 1) * r) + __ldg(bn_beta + c + 1);
                    v.z = v.z * (__ldg(bn_gamma + c + 2) * r) + __ldg(bn_beta + c + 2);
                    v.w = v.w * (__ldg(bn_gamma + c + 3) * r) + __ldg(bn_beta + c + 3);
                }
                *(float4*)&sm.sEin[el * 36 + off + 4 * q] = v;
            }
        }
    }
    __syncthreads();

    // ---- GEMM1: H[128x64] = relu(s[src]+d[dst]+uWe[bs] + Ein[128x32] @ We[32x64]) ----
    {
        int tx = tid & 15, ty = tid >> 4;
        int r0 = ty * 8, c0 = tx * 4;
        ull acc0[8], acc1[8];
#pragma unroll
        for (int i = 0; i < 8; i++) {
            int s = sm.sSrc[r0 + i], d = sm.sDst[r0 + i], bs = sm.sBs[r0 + i];
            float4 a = *(const float4*)(g_s + (size_t)s * 64 + c0);
            float4 b = *(const float4*)(g_d + (size_t)d * 64 + c0);
            const float* up = sm.sU + bs * 64 + c0;
            PK2(acc0[i], a.x + b.x + up[0], a.y + b.y + up[1]);
            PK2(acc1[i], a.z + b.z + up[2], a.w + b.w + up[3]);
        }
#pragma unroll
        for (int k = 0; k < 32; k++) {
            F4U w; w.f = *(float4*)&sm.sWe[k * 64 + c0];
#pragma unroll
            for (int i = 0; i < 8; i++) {
                float ev = sm.sEin[(r0 + i) * 36 + k];
                ull evp; PK2(evp, ev, ev);
                FMA2(acc0[i], evp, w.u[0], acc0[i]);
                FMA2(acc1[i], evp, w.u[1], acc1[i]);
            }
        }
#pragma unroll
        for (int i = 0; i < 8; i++) {
            float4 r;
            UPK2(r.x, r.y, acc0[i]);
            UPK2(r.z, r.w, acc1[i]);
            r.x = fmaxf(r.x, 0.f); r.y = fmaxf(r.y, 0.f);
            r.z = fmaxf(r.z, 0.f); r.w = fmaxf(r.w, 0.f);
            *(float4*)&sm.sH[(r0 + i) * 68 + c0] = r;
        }
    }
    __syncthreads();

    // ---- GEMM2: O[128x32] = H @ W2[64x32] + b2; write e; scatter-add to agg ----
    {
        int tx2 = tid & 7, ty2 = tid >> 3;
        int r0 = ty2 * 4, c0 = tx2 * 4;
        ull o0[4], o1[4];
        {
            float4 bb = *(float4*)&sm.sb2[c0];
            ull b0, b1; PK2(b0, bb.x, bb.y); PK2(b1, bb.z, bb.w);
#pragma unroll
            for (int i = 0; i < 4; i++) { o0[i] = b0; o1[i] = b1; }
        }
#pragma unroll
        for (int k = 0; k < 64; k++) {
            F4U w; w.f = *(float4*)&sm.sW2[k * 32 + c0];
#pragma unroll
            for (int i = 0; i < 4; i++) {
                float hv = sm.sH[(r0 + i) * 68 + k];
                ull hp; PK2(hp, hv, hv);
                FMA2(o0[i], hp, w.u[0], o0[i]);
                FMA2(o1[i], hp, w.u[1], o1[i]);
            }
        }
#pragma unroll
        for (int i = 0; i < 4; i++) {
            int e = eBase + r0 + i;
            if (e < E) {
                float4 o;
                UPK2(o.x, o.y, o0[i]);
                UPK2(o.z, o.w, o1[i]);
                *(float4*)(eout + (size_t)e * 32 + c0) = o;
                float* ap = g_agg + (size_t)sm.sDst[r0 + i] * 32 + c0;
                asm volatile("red.global.add.v4.f32 [%0], {%1,%2,%3,%4};"
                             :: "l"(ap), "f"(o.x), "f"(o.y), "f"(o.z), "f"(o.w)
                             : "memory");
            }
        }
    }
}

// node model: x = MLP([x, agg/deg, u[batch]]), plus batch-sum via shared bins
__global__ void __launch_bounds__(256) node_k(const float* __restrict__ x_in,
                                              float* __restrict__ x_out,
                                              const int* __restrict__ batch,
                                              const float* __restrict__ W1n,  // rows [0:64)
                                              const float* __restrict__ W2n,
                                              const float* __restrict__ b2n, int N) {
    __shared__ float sWx[2048];
    __shared__ float sWa[2048];
    __shared__ float sW2[2048];
    __shared__ float sU[1024];
    __shared__ float sb2[32];
    __shared__ float sB[MAXB * 32];
    int tid = threadIdx.x;
    for (int i = tid; i < 2048; i += 256) {
        sWx[i] = W1n[i];
        sWa[i] = W1n[2048 + i];
        sW2[i] = W2n[i];
    }
    for (int i = tid; i < 1024; i += 256) sU[i] = g_uWn[i];
    if (tid < 32) sb2[tid] = b2n[tid];
    for (int i = tid; i < MAXB * 32; i += 256) sB[i] = 0.f;
    __syncthreads();

    int n = blockIdx.x * 256 + tid;
    if (n < N) {
        int b = batch[n];
        float xv[32], av[32];
        float inv = 1.f / fmaxf(g_deg[n], 1.f);
        const float4* xp = (const float4*)(x_in + (size_t)n * 32);
        const float4* ap = (const float4*)(g_agg + (size_t)n * 32);
#pragma unroll
        for (int k = 0; k < 8; k++) {
            float4 v = xp[k];
            xv[4 * k] = v.x; xv[4 * k + 1] = v.y; xv[4 * k + 2] = v.z; xv[4 * k + 3] = v.w;
            float4 a = ap[k];
            av[4 * k] = a.x * inv; av[4 * k + 1] = a.y * inv;
            av[4 * k + 2] = a.z * inv; av[4 * k + 3] = a.w * inv;
        }
        ull hp[32];
        {
            const float4* up4 = (const float4*)(sU + b * 64);
#pragma unroll
            for (int j4 = 0; j4 < 16; j4++) {
                F4U u; u.f = up4[j4];
                hp[2 * j4] = u.u[0];
                hp[2 * j4 + 1] = u.u[1];
            }
        }
#pragma unroll 2
        for (int k = 0; k < 32; k++) {
            ull xkp, akp;
            PK2(xkp, xv[k], xv[k]);
            PK2(akp, av[k], av[k]);
#pragma unroll
            for (int j4 = 0; j4 < 16; j4++) {
                F4U wx; wx.f = *(const float4*)&sWx[k * 64 + j4 * 4];
                F4U wa; wa.f = *(const float4*)&sWa[k * 64 + j4 * 4];
                FMA2(hp[2 * j4], xkp, wx.u[0], hp[2 * j4]);
                FMA2(hp[2 * j4 + 1], xkp, wx.u[1], hp[2 * j4 + 1]);
                FMA2(hp[2 * j4], akp, wa.u[0], hp[2 * j4]);
                FMA2(hp[2 * j4 + 1], akp, wa.u[1], hp[2 * j4 + 1]);
            }
        }
        float h[64];
#pragma unroll
        for (int j2 = 0; j2 < 32; j2++) {
            float lo, hi;
            UPK2(lo, hi, hp[j2]);
            h[2 * j2] = fmaxf(lo, 0.f);
            h[2 * j2 + 1] = fmaxf(hi, 0.f);
        }

        ull o0[8], o1[8];  // 32 outputs as 16 pairs -> use 8x float4 layout
        ull op[16];
        {
            const float4* bb4 = (const float4*)sb2;
#pragma unroll
            for (int j4 = 0; j4 < 8; j4++) {
                F4U u; u.f = bb4[j4];
                op[2 * j4] = u.u[0];
                op[2 * j4 + 1] = u.u[1];
            }
        }
#pragma unroll 4
        for (int k = 0; k < 64; k++) {
            ull hkp; PK2(hkp, h[k], h[k]);
#pragma unroll
            for (int j4 = 0; j4 < 8; j4++) {
                F4U w; w.f = *(const float4*)&sW2[k * 32 + j4 * 4];
                FMA2(op[2 * j4], hkp, w.u[0], op[2 * j4]);
                FMA2(op[2 * j4 + 1], hkp, w.u[1], op[2 * j4 + 1]);
            }
        }
        float o[32];
#pragma unroll
        for (int j2 = 0; j2 < 16; j2++) {
            UPK2(o[2 * j2], o[2 * j2 + 1], op[j2]);
        }
        float4* xo = (float4*)(x_out + (size_t)n * 32);
#pragma unroll
        for (int i = 0; i < 8; i++)
            xo[i] = make_float4(o[4 * i], o[4 * i + 1], o[4 * i + 2], o[4 * i + 3]);
        float* bp = sB + b * 32;
#pragma unroll
        for (int i = 0; i < 32; i++) atomicAdd(bp + i, o[i]);
        (void)o0; (void)o1;
    }
    __syncthreads();
    for (int i = tid; i < MAXB * 32; i += 256) atomicAdd(&g_bsum[i], sB[i]);
}

// global model: u = MLP([u, bsum/gcnt])
__global__ void glob_k(const float* __restrict__ W1g, const float* __restrict__ b1g,
                       const float* __restrict__ W2g, const float* __restrict__ b2g,
                       float* __restrict__ out_u, int writeOut) {
    int b = blockIdx.x;
    int j = threadIdx.x;  // 64 threads
    __shared__ float gi[64];
    __shared__ float h[64];
    if (j < 32) gi[j] = g_u[b * 32 + j];
    else        gi[j] = g_bsum[b * 32 + (j - 32)] / fmaxf(g_gcnt[b], 1.f);
    __syncthreads();
    float acc = b1g[j];
#pragma unroll
    for (int k = 0; k < 64; k++) acc += gi[k] * W1g[k * 64 + j];
    h[j] = fmaxf(acc, 0.f);
    __syncthreads();
    if (j < 32) {
        float a2 = b2g[j];
#pragma unroll
        for (int k = 0; k < 64; k++) a2 += h[k] * W2g[k * 32 + j];
        g_u[b * 32 + j] = a2;
        if (writeOut) out_u[b * 32 + j] = a2;
    }
}

// ---------------- host launcher ----------------
extern "C" void kernel_launch(void* const* d_in, const int* in_sizes, int n_in,
                              void* d_out, int out_size) {
    const float* node_feats = (const float*)d_in[0];
    const int*   edge_index = (const int*)d_in[1];
    const float* edge_feats = (const float*)d_in[2];
    const float* glob_feats = (const float*)d_in[3];
    const int*   batch      = (const int*)d_in[4];
    const float* node_gamma = (const float*)d_in[5];
    const float* node_beta  = (const float*)d_in[6];
    const float* edge_gamma = (const float*)d_in[7];
    const float* edge_beta  = (const float*)d_in[8];
    const float* glob_gamma = (const float*)d_in[9];
    const float* glob_beta  = (const float*)d_in[10];
    const float* edge_W1 = (const float*)d_in[11];
    const float* edge_b1 = (const float*)d_in[12];
    const float* edge_W2 = (const float*)d_in[13];
    const float* edge_b2 = (const float*)d_in[14];
    const float* node_W1 = (const float*)d_in[15];
    const float* node_b1 = (const float*)d_in[16];
    const float* node_W2 = (const float*)d_in[17];
    const float* node_b2 = (const float*)d_in[18];
    const float* glob_W1 = (const float*)d_in[19];
    const float* glob_b1 = (const float*)d_in[20];
    const float* glob_W2 = (const float*)d_in[21];
    const float* glob_b2 = (const float*)d_in[22];

    const int N = in_sizes[0] / 32;
    const int E = in_sizes[1] / 2;
    const int B = in_sizes[3] / 32;
    const int* srcA = edge_index;
    const int* dstA = edge_index + E;

    float* out   = (float*)d_out;
    float* out_x = out;
    float* out_e = out + (size_t)N * 32;
    float* out_u = out_e + (size_t)E * 32;

    float *xa, *xb, *up, *degp, *gcntp, *aggp, *bsump;
    cudaGetSymbolAddress((void**)&xa, g_xa);
    cudaGetSymbolAddress((void**)&xb, g_xb);
    cudaGetSymbolAddress((void**)&up, g_u);
    cudaGetSymbolAddress((void**)&degp, g_deg);
    cudaGetSymbolAddress((void**)&gcntp, g_gcnt);
    cudaGetSymbolAddress((void**)&aggp, g_agg);
    cudaGetSymbolAddress((void**)&bsump, g_bsum);

    static bool attr_set = false;
    if (!attr_set) {
        cudaFuncSetAttribute(edge2_k, cudaFuncAttributeMaxDynamicSharedMemorySize,
                             (int)sizeof(ESm));
        attr_set = true;
    }

    // input BN (node, global; edge BN fused into layer-0 edge kernel)
    bn_k<<<(N * 32 + 255) / 256, 256>>>(node_feats, node_gamma, node_beta, xa, N * 32);
    bn_k<<<(B * 32 + 255) / 256, 256>>>(glob_feats, glob_gamma, glob_beta, up, B * 32);

    // fixed index-structure denominators
    zero_k<<<(N + 255) / 256, 256>>>(degp, N);
    zero_k<<<1, 256>>>(gcntp, B);
    deg_k<<<(E + 255) / 256, 256>>>(dstA, E);
    gcnt_k<<<(N + 255) / 256, 256>>>(batch, N);

    float* xcur = xa;
    int eblocks = (E + TE - 1) / TE;
    for (int l = 0; l < 3; l++) {
        float* xnext = (l == 2) ? out_x : ((xcur == xa) ? xb : xa);

        zero_k<<<(N * 32 + 255) / 256, 256>>>(aggp, N * 32);
        zero_k<<<1, 512>>>(bsump, B * 32);

        uw_k<<<B, 128>>>(edge_W1 + l * 8192 + 96 * 64, edge_b1 + l * 64,
                         node_W1 + l * 6144 + 64 * 64, node_b1 + l * 64);
        sd_k<<<(N + 255) / 256, 256>>>(xcur, edge_W1 + l * 8192, N);
        edge2_k<<<eblocks, 256, sizeof(ESm)>>>(
            srcA, dstA, batch,
            edge_W1 + l * 8192 + 64 * 64,
            edge_W2 + l * 2048, edge_b2 + l * 32,
            (l == 0) ? edge_feats : out_e,
            (l == 0) ? edge_gamma : nullptr,
            (l == 0) ? edge_beta : nullptr,
            out_e, E);
        node_k<<<(N + 255) / 256, 256>>>(xcur, xnext, batch,
                                         node_W1 + l * 6144,
                                         node_W2 + l * 2048, node_b2 + l * 32, N);
        glob_k<<<B, 64>>>(glob_W1 + l * 4096, glob_b1 + l * 64,
                          glob_W2 + l * 2048, glob_b2 + l * 32, out_u, (l == 2) ? 1 : 0);
        xcur = xnext;
    }
}